// round 13
// baseline (speedup 1.0000x reference)
#include <cuda_runtime.h>
#include <cstdint>

// Model_PDE_2: N=131072, H=1024, D=2.  tf32 mma.sync, R11:
// - H-split: CTA (ptile, half) does 128 points x 512 h (14.5KB smem, high occ)
// - no setup kernel: derived weights computed inline while staging smem;
//   C0/C1 eliminated via u = 1 - t^2 accumulated directly.
//
//   per (n,h): z = x0*a+x1*b+c; t = tanh(z); u = 1-t^2; t3 = t*u
//   D[32pts x 8] += A * B sparse:
//     col0: out = sum t*w ; col1: g0 = sum u*wa ; col2: g1 = sum u*wb
//     col3: dx = sum t3*wbb   (wbb = -2*w*b^2)
//   pde = .5*x1^2 + g0 + .5*dx + .5*x1*g1 - (.25/3.6)*g1^2
// Output: d_out[0..N)=out, d_out[N..2N)=pde.

#define HID 1024
#define HHALF 512
#define TPB 128
#define NTRI_H (HHALF / 8)  // 64 triples per half
#define WT_STRIDE 520       // rows offset by 8 banks -> conflict-free
#define NMAX 131072

__device__ float2 g_pA[2 * NMAX];  // per-half partials {out, g0}
__device__ float2 g_pB[2 * NMAX];  // per-half partials {g1, dx}

__device__ __forceinline__ float tanh_fast(float z) {
    float t;
    asm("tanh.approx.f32 %0, %1;" : "=f"(t) : "f"(z));
    return t;
}

__device__ __forceinline__ void mma_tf32(float* d, float a0, float a1, float a2,
                                         float a3, float b0, float b1) {
    asm volatile(
        "mma.sync.aligned.m16n8k8.row.col.f32.tf32.tf32.f32 "
        "{%0,%1,%2,%3}, {%4,%5,%6,%7}, {%8,%9}, {%0,%1,%2,%3};"
        : "+f"(d[0]), "+f"(d[1]), "+f"(d[2]), "+f"(d[3])
        : "r"(__float_as_uint(a0)), "r"(__float_as_uint(a1)),
          "r"(__float_as_uint(a2)), "r"(__float_as_uint(a3)),
          "r"(__float_as_uint(b0)), "r"(__float_as_uint(b1)));
}

__global__ __launch_bounds__(TPB) void pde_main(const float* __restrict__ x,
                                                const float* __restrict__ W1,
                                                const float* __restrict__ b1,
                                                const float* __restrict__ w2,
                                                int N) {
    __shared__ float2 s_ab[HHALF];          // 4 KB
    __shared__ float s_cc[HHALF];           // 2 KB
    __shared__ float s_wt[4 * WT_STRIDE];   // 8.3 KB

    int tid = threadIdx.x;
    int half = blockIdx.x & 1;
    int ptile = blockIdx.x >> 1;
    int hoff = half * HHALF;

    // Stage + derive weights inline (W1/b1/w2 slice is L2-resident).
    for (int i = tid; i < HHALF; i += TPB) {
        int h = hoff + i;
        float2 ab = reinterpret_cast<const float2*>(W1)[h];
        float c = b1[h];
        float w = w2[h];
        s_ab[i] = ab;
        s_cc[i] = c;
        s_wt[0 * WT_STRIDE + i] = w;                       // w
        s_wt[1 * WT_STRIDE + i] = w * ab.x;                // wa
        s_wt[2 * WT_STRIDE + i] = w * ab.y;                // wb
        s_wt[3 * WT_STRIDE + i] = -2.0f * w * ab.y * ab.y; // wbb
    }
    __syncthreads();

    int lane = tid & 31;
    int wid = tid >> 5;
    int g = lane >> 2;   // group id = output column n, also row base
    int tig = lane & 3;  // thread-in-group = k sub-col
    int n = g;
    // Octet in which this column's B entry is nonzero:
    // n=0 (w, t): j=0 ; n=1,2 (wa,wb with u): j=1 ; n=3 (wbb, t3): j=2
    int jn = (n == 0) ? 0 : (n <= 2) ? 1 : (n == 3) ? 2 : -1;
    bool has_b = (n < 4);
    const float* wtp = s_wt + (n & 3) * WT_STRIDE;

    int base_pt = ptile * TPB + wid * 32;

    float2 myx = reinterpret_cast<const float2*>(x)[base_pt + lane];
    float x0r[4], x1r[4];
#pragma unroll
    for (int i = 0; i < 4; i++) {
        x0r[i] = __shfl_sync(0xffffffffu, myx.x, g + 8 * i);
        x1r[i] = __shfl_sync(0xffffffffu, myx.y, g + 8 * i);
    }

    float acc0[4] = {0.f, 0.f, 0.f, 0.f};  // rows g, g+8
    float acc1[4] = {0.f, 0.f, 0.f, 0.f};  // rows g+16, g+24

#pragma unroll 2
    for (int tr = 0; tr < NTRI_H; tr++) {
        int h0 = tr * 8 + tig;
        int h1 = h0 + 4;
        float2 ab0 = s_ab[h0];
        float2 ab1 = s_ab[h1];
        float cc0 = s_cc[h0];
        float cc1 = s_cc[h1];
        float w0 = 0.f, w1 = 0.f;
        if (has_b) {
            w0 = wtp[h0];
            w1 = wtp[h1];
        }

        // Stage 1: t -> mma octet 0
        float t[4][2];
#pragma unroll
        for (int r = 0; r < 4; r++) {
            float z0 = __fmaf_rn(x1r[r], ab0.y, __fmaf_rn(x0r[r], ab0.x, cc0));
            t[r][0] = tanh_fast(z0);
            float z1 = __fmaf_rn(x1r[r], ab1.y, __fmaf_rn(x0r[r], ab1.x, cc1));
            t[r][1] = tanh_fast(z1);
        }
        {
            float b0 = (jn == 0) ? w0 : 0.f;
            float b1 = (jn == 0) ? w1 : 0.f;
            mma_tf32(acc0, t[0][0], t[1][0], t[0][1], t[1][1], b0, b1);
            mma_tf32(acc1, t[2][0], t[3][0], t[2][1], t[3][1], b0, b1);
        }
        // Stage 2: u = 1 - t^2 -> mma octet 1
        float u[4][2];
#pragma unroll
        for (int r = 0; r < 4; r++) {
            u[r][0] = __fmaf_rn(-t[r][0], t[r][0], 1.0f);
            u[r][1] = __fmaf_rn(-t[r][1], t[r][1], 1.0f);
        }
        {
            float b0 = (jn == 1) ? w0 : 0.f;
            float b1 = (jn == 1) ? w1 : 0.f;
            mma_tf32(acc0, u[0][0], u[1][0], u[0][1], u[1][1], b0, b1);
            mma_tf32(acc1, u[2][0], u[3][0], u[2][1], u[3][1], b0, b1);
        }
        // Stage 3: t3 = t * u (in place) -> mma octet 2
#pragma unroll
        for (int r = 0; r < 4; r++) {
            t[r][0] = t[r][0] * u[r][0];
            t[r][1] = t[r][1] * u[r][1];
        }
        {
            float b0 = (jn == 2) ? w0 : 0.f;
            float b1 = (jn == 2) ? w1 : 0.f;
            mma_tf32(acc0, t[0][0], t[1][0], t[0][1], t[1][1], b0, b1);
            mma_tf32(acc1, t[2][0], t[3][0], t[2][1], t[3][1], b0, b1);
        }
    }

    // Partial store: tig0 holds cols {0,1} = {out, g0}; tig1 holds {2,3} = {g1, dx}.
    int sbase = half * NMAX + base_pt + g;
    if (tig == 0) {
        g_pA[sbase + 0] = make_float2(acc0[0], acc0[1]);
        g_pA[sbase + 8] = make_float2(acc0[2], acc0[3]);
        g_pA[sbase + 16] = make_float2(acc1[0], acc1[1]);
        g_pA[sbase + 24] = make_float2(acc1[2], acc1[3]);
    } else if (tig == 1) {
        g_pB[sbase + 0] = make_float2(acc0[0], acc0[1]);
        g_pB[sbase + 8] = make_float2(acc0[2], acc0[3]);
        g_pB[sbase + 16] = make_float2(acc1[0], acc1[1]);
        g_pB[sbase + 24] = make_float2(acc1[2], acc1[3]);
    }
}

__global__ __launch_bounds__(256) void pde_epilogue(const float* __restrict__ x,
                                                    const float* __restrict__ b2,
                                                    float* __restrict__ out,
                                                    int N) {
    int p = blockIdx.x * 256 + threadIdx.x;
    if (p >= N) return;

    float2 a0 = g_pA[p];
    float2 a1 = g_pA[NMAX + p];
    float2 bb0 = g_pB[p];
    float2 bb1 = g_pB[NMAX + p];
    float2 xv = reinterpret_cast<const float2*>(x)[p];
    float x1 = xv.y;

    float ov = a0.x + a1.x;
    float g0 = a0.y + a1.y;
    float g1 = bb0.x + bb1.x;
    float dx = bb0.y + bb1.y;

    float pde = __fmaf_rn(0.5f * x1, x1, g0);
    pde = __fmaf_rn(0.5f, dx, pde);
    pde = __fmaf_rn(0.5f * x1, g1, pde);
    pde = __fmaf_rn(-0.069444444444444444f * g1, g1, pde);

    out[p] = ov + b2[0];
    out[N + p] = pde;
}

extern "C" void kernel_launch(void* const* d_in, const int* in_sizes, int n_in,
                              void* d_out, int out_size) {
    const float* x = (const float*)d_in[0];
    const float* W1 = (const float*)d_in[1];
    const float* b1 = (const float*)d_in[2];
    const float* w2 = (const float*)d_in[3];
    const float* b2 = (const float*)d_in[4];
    int N = in_sizes[0] / 2;

    pde_main<<<(N / TPB) * 2, TPB>>>(x, W1, b1, w2, N);
    pde_epilogue<<<(N + 255) / 256, 256>>>(x, b2, (float*)d_out, N);
}

// round 14
// speedup vs baseline: 1.0052x; 1.0052x over previous
#include <cuda_runtime.h>
#include <cstdint>

// Model_PDE_2: N=131072, H=1024, D=2.  tf32 mma.sync, R14:
// - H-split: CTA (ptile, half) does 128 points x 512 h (14.5KB smem)
// - inline weight derivation (no setup kernel)
// - FUSED epilogue: second-finishing CTA of each ptile folds both halves and
//   writes out/pde (threadfence-reduction pattern), ticket reset for graph replay.
//
//   per (n,h): z = x0*a+x1*b+c; t = tanh(z); u = 1-t^2; t3 = t*u
//   D[32pts x 8] += A * B sparse:
//     col0: out = sum t*w ; col1: g0 = sum u*wa ; col2: g1 = sum u*wb
//     col3: dx = sum t3*wbb   (wbb = -2*w*b^2)
//   pde = .5*x1^2 + g0 + .5*dx + .5*x1*g1 - (.25/3.6)*g1^2
// Output: d_out[0..N)=out, d_out[N..2N)=pde.

#define HID 1024
#define HHALF 512
#define TPB 128
#define NTRI_H (HHALF / 8)  // 64 triples per half
#define WT_STRIDE 520       // rows offset by 8 banks -> conflict-free
#define NMAX 131072
#define NPTILE (NMAX / TPB)

__device__ float2 g_pA[2 * NMAX];     // per-half partials {out, g0}
__device__ float2 g_pB[2 * NMAX];     // per-half partials {g1, dx}
__device__ int g_ticket[NPTILE];      // zero-initialized; reset each run

__device__ __forceinline__ float tanh_fast(float z) {
    float t;
    asm("tanh.approx.f32 %0, %1;" : "=f"(t) : "f"(z));
    return t;
}

__device__ __forceinline__ void mma_tf32(float* d, float a0, float a1, float a2,
                                         float a3, float b0, float b1) {
    asm volatile(
        "mma.sync.aligned.m16n8k8.row.col.f32.tf32.tf32.f32 "
        "{%0,%1,%2,%3}, {%4,%5,%6,%7}, {%8,%9}, {%0,%1,%2,%3};"
        : "+f"(d[0]), "+f"(d[1]), "+f"(d[2]), "+f"(d[3])
        : "r"(__float_as_uint(a0)), "r"(__float_as_uint(a1)),
          "r"(__float_as_uint(a2)), "r"(__float_as_uint(a3)),
          "r"(__float_as_uint(b0)), "r"(__float_as_uint(b1)));
}

__global__ __launch_bounds__(TPB) void pde_main(const float* __restrict__ x,
                                                const float* __restrict__ W1,
                                                const float* __restrict__ b1,
                                                const float* __restrict__ w2,
                                                const float* __restrict__ b2,
                                                float* __restrict__ out,
                                                int N) {
    __shared__ float2 s_ab[HHALF];          // 4 KB
    __shared__ float s_cc[HHALF];           // 2 KB
    __shared__ float s_wt[4 * WT_STRIDE];   // 8.3 KB
    __shared__ int s_ticket;

    int tid = threadIdx.x;
    int half = blockIdx.x & 1;
    int ptile = blockIdx.x >> 1;
    int hoff = half * HHALF;

    // Stage + derive weights inline (W1/b1/w2 slice is L2-resident).
    for (int i = tid; i < HHALF; i += TPB) {
        int h = hoff + i;
        float2 ab = reinterpret_cast<const float2*>(W1)[h];
        float c = b1[h];
        float w = w2[h];
        s_ab[i] = ab;
        s_cc[i] = c;
        s_wt[0 * WT_STRIDE + i] = w;                       // w
        s_wt[1 * WT_STRIDE + i] = w * ab.x;                // wa
        s_wt[2 * WT_STRIDE + i] = w * ab.y;                // wb
        s_wt[3 * WT_STRIDE + i] = -2.0f * w * ab.y * ab.y; // wbb
    }
    __syncthreads();

    int lane = tid & 31;
    int wid = tid >> 5;
    int g = lane >> 2;   // group id = output column n, also row base
    int tig = lane & 3;  // thread-in-group = k sub-col
    int n = g;
    // Octet in which this column's B entry is nonzero:
    // n=0 (w, t): j=0 ; n=1,2 (wa,wb with u): j=1 ; n=3 (wbb, t3): j=2
    int jn = (n == 0) ? 0 : (n <= 2) ? 1 : (n == 3) ? 2 : -1;
    bool has_b = (n < 4);
    const float* wtp = s_wt + (n & 3) * WT_STRIDE;

    int base_pt = ptile * TPB + wid * 32;

    float2 myx = reinterpret_cast<const float2*>(x)[base_pt + lane];
    float x0r[4], x1r[4];
#pragma unroll
    for (int i = 0; i < 4; i++) {
        x0r[i] = __shfl_sync(0xffffffffu, myx.x, g + 8 * i);
        x1r[i] = __shfl_sync(0xffffffffu, myx.y, g + 8 * i);
    }

    float acc0[4] = {0.f, 0.f, 0.f, 0.f};  // rows g, g+8
    float acc1[4] = {0.f, 0.f, 0.f, 0.f};  // rows g+16, g+24

#pragma unroll 2
    for (int tr = 0; tr < NTRI_H; tr++) {
        int h0 = tr * 8 + tig;
        int h1 = h0 + 4;
        float2 ab0 = s_ab[h0];
        float2 ab1 = s_ab[h1];
        float cc0 = s_cc[h0];
        float cc1 = s_cc[h1];
        float w0 = 0.f, w1 = 0.f;
        if (has_b) {
            w0 = wtp[h0];
            w1 = wtp[h1];
        }

        // Stage 1: t -> mma octet 0
        float t[4][2];
#pragma unroll
        for (int r = 0; r < 4; r++) {
            float z0 = __fmaf_rn(x1r[r], ab0.y, __fmaf_rn(x0r[r], ab0.x, cc0));
            t[r][0] = tanh_fast(z0);
            float z1 = __fmaf_rn(x1r[r], ab1.y, __fmaf_rn(x0r[r], ab1.x, cc1));
            t[r][1] = tanh_fast(z1);
        }
        {
            float b0 = (jn == 0) ? w0 : 0.f;
            float b1v = (jn == 0) ? w1 : 0.f;
            mma_tf32(acc0, t[0][0], t[1][0], t[0][1], t[1][1], b0, b1v);
            mma_tf32(acc1, t[2][0], t[3][0], t[2][1], t[3][1], b0, b1v);
        }
        // Stage 2: u = 1 - t^2 -> mma octet 1
        float u[4][2];
#pragma unroll
        for (int r = 0; r < 4; r++) {
            u[r][0] = __fmaf_rn(-t[r][0], t[r][0], 1.0f);
            u[r][1] = __fmaf_rn(-t[r][1], t[r][1], 1.0f);
        }
        {
            float b0 = (jn == 1) ? w0 : 0.f;
            float b1v = (jn == 1) ? w1 : 0.f;
            mma_tf32(acc0, u[0][0], u[1][0], u[0][1], u[1][1], b0, b1v);
            mma_tf32(acc1, u[2][0], u[3][0], u[2][1], u[3][1], b0, b1v);
        }
        // Stage 3: t3 = t * u (in place) -> mma octet 2
#pragma unroll
        for (int r = 0; r < 4; r++) {
            t[r][0] = t[r][0] * u[r][0];
            t[r][1] = t[r][1] * u[r][1];
        }
        {
            float b0 = (jn == 2) ? w0 : 0.f;
            float b1v = (jn == 2) ? w1 : 0.f;
            mma_tf32(acc0, t[0][0], t[1][0], t[0][1], t[1][1], b0, b1v);
            mma_tf32(acc1, t[2][0], t[3][0], t[2][1], t[3][1], b0, b1v);
        }
    }

    // Partial store: tig0 holds cols {0,1} = {out, g0}; tig1 holds {2,3} = {g1, dx}.
    int sbase = half * NMAX + base_pt + g;
    if (tig == 0) {
        g_pA[sbase + 0] = make_float2(acc0[0], acc0[1]);
        g_pA[sbase + 8] = make_float2(acc0[2], acc0[3]);
        g_pA[sbase + 16] = make_float2(acc1[0], acc1[1]);
        g_pA[sbase + 24] = make_float2(acc1[2], acc1[3]);
    } else if (tig == 1) {
        g_pB[sbase + 0] = make_float2(acc0[0], acc0[1]);
        g_pB[sbase + 8] = make_float2(acc0[2], acc0[3]);
        g_pB[sbase + 16] = make_float2(acc1[0], acc1[1]);
        g_pB[sbase + 24] = make_float2(acc1[2], acc1[3]);
    }

    // ---- fused fold: second-arriving CTA of this ptile finalizes ----
    __threadfence();  // make partials visible before ticket bump
    __syncthreads();  // all warps' stores issued before tid0 signals
    if (tid == 0) s_ticket = atomicAdd(&g_ticket[ptile], 1);
    __syncthreads();
    if (s_ticket == 1) {
        int p = ptile * TPB + tid;  // one point per thread
        float2 a0 = g_pA[p];
        float2 a1 = g_pA[NMAX + p];
        float2 bb0 = g_pB[p];
        float2 bb1 = g_pB[NMAX + p];
        float x1v = reinterpret_cast<const float2*>(x)[p].y;

        float ov = a0.x + a1.x;
        float g0v = a0.y + a1.y;
        float g1v = bb0.x + bb1.x;
        float dxv = bb0.y + bb1.y;

        float pde = __fmaf_rn(0.5f * x1v, x1v, g0v);
        pde = __fmaf_rn(0.5f, dxv, pde);
        pde = __fmaf_rn(0.5f * x1v, g1v, pde);
        pde = __fmaf_rn(-0.069444444444444444f * g1v, g1v, pde);

        out[p] = ov + b2[0];
        out[N + p] = pde;

        if (tid == 0) g_ticket[ptile] = 0;  // reset for next graph replay
    }
}

extern "C" void kernel_launch(void* const* d_in, const int* in_sizes, int n_in,
                              void* d_out, int out_size) {
    const float* x = (const float*)d_in[0];
    const float* W1 = (const float*)d_in[1];
    const float* b1 = (const float*)d_in[2];
    const float* w2 = (const float*)d_in[3];
    const float* b2 = (const float*)d_in[4];
    int N = in_sizes[0] / 2;

    pde_main<<<(N / TPB) * 2, TPB>>>(x, W1, b1, w2, b2, (float*)d_out, N);
}

// round 15
// speedup vs baseline: 1.1015x; 1.0958x over previous
#include <cuda_runtime.h>
#include <cstdint>

// Model_PDE_2: N=131072, H=1024, D=2.  tf32 mma.sync, R15:
// - H-split halves (512 h per CTA) + 2 point-tiles per warp (64 pts/warp,
//   256 pts/CTA) -> grid 1024 = single resident wave, 2x ILP per warp.
// - {a,b,c,w} packed float4 (LDS.128); wt table rows {wa,wb,wbb}.
// - fused fold epilogue (second CTA of each ptile finalizes 256 points).
//
//   per (n,h): z = x0*a+x1*b+c; t = tanh(z); u = 1-t^2; t3 = t*u
//   col0: out = sum t*w ; col1: g0 = sum u*wa ; col2: g1 = sum u*wb
//   col3: dx = sum t3*wbb   (wbb = -2*w*b^2)
//   pde = .5*x1^2 + g0 + .5*dx + .5*x1*g1 - (.25/3.6)*g1^2
// Output: d_out[0..N)=out, d_out[N..2N)=pde.

#define HID 1024
#define HHALF 512
#define TPB 128
#define CTA_PTS 256
#define NTRI_H (HHALF / 8)  // 64 triples
#define WT_STRIDE 520       // rows offset by 8 banks
#define NMAX 131072
#define NPTILE (NMAX / CTA_PTS)  // 512

__device__ float2 g_pA[2 * NMAX];  // per-half partials {out, g0}
__device__ float2 g_pB[2 * NMAX];  // per-half partials {g1, dx}
__device__ int g_ticket[NPTILE];   // zero-init; reset each run

__device__ __forceinline__ float tanh_fast(float z) {
    float t;
    asm("tanh.approx.f32 %0, %1;" : "=f"(t) : "f"(z));
    return t;
}

__device__ __forceinline__ void mma_tf32(float* d, float a0, float a1, float a2,
                                         float a3, float b0, float b1) {
    asm volatile(
        "mma.sync.aligned.m16n8k8.row.col.f32.tf32.tf32.f32 "
        "{%0,%1,%2,%3}, {%4,%5,%6,%7}, {%8,%9}, {%0,%1,%2,%3};"
        : "+f"(d[0]), "+f"(d[1]), "+f"(d[2]), "+f"(d[3])
        : "r"(__float_as_uint(a0)), "r"(__float_as_uint(a1)),
          "r"(__float_as_uint(a2)), "r"(__float_as_uint(a3)),
          "r"(__float_as_uint(b0)), "r"(__float_as_uint(b1)));
}

__global__ __launch_bounds__(TPB, 7) void pde_main(
    const float* __restrict__ x, const float* __restrict__ W1,
    const float* __restrict__ b1, const float* __restrict__ w2,
    const float* __restrict__ b2, float* __restrict__ out, int N) {
    __shared__ float4 s_abc[HHALF];        // 8 KB {a,b,c,w}
    __shared__ float s_wt[3 * WT_STRIDE];  // 6.2 KB rows {wa, wb, wbb}
    __shared__ int s_ticket;

    int tid = threadIdx.x;
    int half = blockIdx.x & 1;
    int ptile = blockIdx.x >> 1;
    int hoff = half * HHALF;

    for (int i = tid; i < HHALF; i += TPB) {
        int h = hoff + i;
        float2 ab = reinterpret_cast<const float2*>(W1)[h];
        float c = b1[h];
        float w = w2[h];
        s_abc[i] = make_float4(ab.x, ab.y, c, w);
        s_wt[0 * WT_STRIDE + i] = w * ab.x;                // wa
        s_wt[1 * WT_STRIDE + i] = w * ab.y;                // wb
        s_wt[2 * WT_STRIDE + i] = -2.0f * w * ab.y * ab.y; // wbb
    }
    __syncthreads();

    int lane = tid & 31;
    int wid = tid >> 5;
    int g = lane >> 2;   // output column n / row base
    int tig = lane & 3;  // k sub-col
    int n = g;
    int row = (n >= 1 && n <= 3) ? (n - 1) : 0;
    const float* wtp = s_wt + row * WT_STRIDE;
    bool gate0 = (n == 0);
    bool gate1 = (n == 1 || n == 2);
    bool gate2 = (n == 3);

    int base_pt = ptile * CTA_PTS + wid * 64;

    // Two point tiles: A = base_pt+0..31, B = base_pt+32..63
    float2 mxA = reinterpret_cast<const float2*>(x)[base_pt + lane];
    float2 mxB = reinterpret_cast<const float2*>(x)[base_pt + 32 + lane];
    float x0A[4], x1A[4], x0B[4], x1B[4];
#pragma unroll
    for (int i = 0; i < 4; i++) {
        x0A[i] = __shfl_sync(0xffffffffu, mxA.x, g + 8 * i);
        x1A[i] = __shfl_sync(0xffffffffu, mxA.y, g + 8 * i);
        x0B[i] = __shfl_sync(0xffffffffu, mxB.x, g + 8 * i);
        x1B[i] = __shfl_sync(0xffffffffu, mxB.y, g + 8 * i);
    }

    float accA0[4] = {0.f, 0.f, 0.f, 0.f};
    float accA1[4] = {0.f, 0.f, 0.f, 0.f};
    float accB0[4] = {0.f, 0.f, 0.f, 0.f};
    float accB1[4] = {0.f, 0.f, 0.f, 0.f};

    for (int tr = 0; tr < NTRI_H; tr++) {
        int h0 = tr * 8 + tig;
        int h1 = h0 + 4;
        float4 q0 = s_abc[h0];
        float4 q1 = s_abc[h1];
        float ws0 = wtp[h0];
        float ws1 = wtp[h1];

        float bs0_0 = gate0 ? q0.w : 0.f;
        float bs0_1 = gate0 ? q1.w : 0.f;
        float bs1_0 = gate1 ? ws0 : 0.f;
        float bs1_1 = gate1 ? ws1 : 0.f;
        float bs2_0 = gate2 ? ws0 : 0.f;
        float bs2_1 = gate2 ? ws1 : 0.f;

        float tA[4][2], tB[4][2];
#pragma unroll
        for (int r = 0; r < 4; r++) {
            float zA0 = __fmaf_rn(x1A[r], q0.y, __fmaf_rn(x0A[r], q0.x, q0.z));
            tA[r][0] = tanh_fast(zA0);
            float zA1 = __fmaf_rn(x1A[r], q1.y, __fmaf_rn(x0A[r], q1.x, q1.z));
            tA[r][1] = tanh_fast(zA1);
            float zB0 = __fmaf_rn(x1B[r], q0.y, __fmaf_rn(x0B[r], q0.x, q0.z));
            tB[r][0] = tanh_fast(zB0);
            float zB1 = __fmaf_rn(x1B[r], q1.y, __fmaf_rn(x0B[r], q1.x, q1.z));
            tB[r][1] = tanh_fast(zB1);
        }
        // stage 0: t * w
        mma_tf32(accA0, tA[0][0], tA[1][0], tA[0][1], tA[1][1], bs0_0, bs0_1);
        mma_tf32(accA1, tA[2][0], tA[3][0], tA[2][1], tA[3][1], bs0_0, bs0_1);
        mma_tf32(accB0, tB[0][0], tB[1][0], tB[0][1], tB[1][1], bs0_0, bs0_1);
        mma_tf32(accB1, tB[2][0], tB[3][0], tB[2][1], tB[3][1], bs0_0, bs0_1);

        // stage 1: u = 1 - t^2 against wa/wb
        float uA[4][2], uB[4][2];
#pragma unroll
        for (int r = 0; r < 4; r++) {
            uA[r][0] = __fmaf_rn(-tA[r][0], tA[r][0], 1.0f);
            uA[r][1] = __fmaf_rn(-tA[r][1], tA[r][1], 1.0f);
            uB[r][0] = __fmaf_rn(-tB[r][0], tB[r][0], 1.0f);
            uB[r][1] = __fmaf_rn(-tB[r][1], tB[r][1], 1.0f);
        }
        mma_tf32(accA0, uA[0][0], uA[1][0], uA[0][1], uA[1][1], bs1_0, bs1_1);
        mma_tf32(accA1, uA[2][0], uA[3][0], uA[2][1], uA[3][1], bs1_0, bs1_1);
        mma_tf32(accB0, uB[0][0], uB[1][0], uB[0][1], uB[1][1], bs1_0, bs1_1);
        mma_tf32(accB1, uB[2][0], uB[3][0], uB[2][1], uB[3][1], bs1_0, bs1_1);

        // stage 2: t3 = t*u against wbb (in place)
#pragma unroll
        for (int r = 0; r < 4; r++) {
            tA[r][0] = tA[r][0] * uA[r][0];
            tA[r][1] = tA[r][1] * uA[r][1];
            tB[r][0] = tB[r][0] * uB[r][0];
            tB[r][1] = tB[r][1] * uB[r][1];
        }
        mma_tf32(accA0, tA[0][0], tA[1][0], tA[0][1], tA[1][1], bs2_0, bs2_1);
        mma_tf32(accA1, tA[2][0], tA[3][0], tA[2][1], tA[3][1], bs2_0, bs2_1);
        mma_tf32(accB0, tB[0][0], tB[1][0], tB[0][1], tB[1][1], bs2_0, bs2_1);
        mma_tf32(accB1, tB[2][0], tB[3][0], tB[2][1], tB[3][1], bs2_0, bs2_1);
    }

    // Partial store: tig0 holds cols {0,1} = {out,g0}; tig1 holds {2,3} = {g1,dx}.
    int sA = half * NMAX + base_pt + g;
    int sB = sA + 32;
    if (tig == 0) {
        g_pA[sA + 0] = make_float2(accA0[0], accA0[1]);
        g_pA[sA + 8] = make_float2(accA0[2], accA0[3]);
        g_pA[sA + 16] = make_float2(accA1[0], accA1[1]);
        g_pA[sA + 24] = make_float2(accA1[2], accA1[3]);
        g_pA[sB + 0] = make_float2(accB0[0], accB0[1]);
        g_pA[sB + 8] = make_float2(accB0[2], accB0[3]);
        g_pA[sB + 16] = make_float2(accB1[0], accB1[1]);
        g_pA[sB + 24] = make_float2(accB1[2], accB1[3]);
    } else if (tig == 1) {
        g_pB[sA + 0] = make_float2(accA0[0], accA0[1]);
        g_pB[sA + 8] = make_float2(accA0[2], accA0[3]);
        g_pB[sA + 16] = make_float2(accA1[0], accA1[1]);
        g_pB[sA + 24] = make_float2(accA1[2], accA1[3]);
        g_pB[sB + 0] = make_float2(accB0[0], accB0[1]);
        g_pB[sB + 8] = make_float2(accB0[2], accB0[3]);
        g_pB[sB + 16] = make_float2(accB1[0], accB1[1]);
        g_pB[sB + 24] = make_float2(accB1[2], accB1[3]);
    }

    // ---- fused fold: second-arriving CTA of this ptile finalizes ----
    __threadfence();
    __syncthreads();
    if (tid == 0) s_ticket = atomicAdd(&g_ticket[ptile], 1);
    __syncthreads();
    if (s_ticket == 1) {
        float bz = b2[0];
#pragma unroll
        for (int i = 0; i < CTA_PTS / TPB; i++) {
            int p = ptile * CTA_PTS + i * TPB + tid;
            float2 a0 = g_pA[p];
            float2 a1 = g_pA[NMAX + p];
            float2 bb0 = g_pB[p];
            float2 bb1 = g_pB[NMAX + p];
            float x1v = reinterpret_cast<const float2*>(x)[p].y;

            float ov = a0.x + a1.x;
            float g0v = a0.y + a1.y;
            float g1v = bb0.x + bb1.x;
            float dxv = bb0.y + bb1.y;

            float pde = __fmaf_rn(0.5f * x1v, x1v, g0v);
            pde = __fmaf_rn(0.5f, dxv, pde);
            pde = __fmaf_rn(0.5f * x1v, g1v, pde);
            pde = __fmaf_rn(-0.069444444444444444f * g1v, g1v, pde);

            out[p] = ov + bz;
            out[N + p] = pde;
        }
        if (tid == 0) g_ticket[ptile] = 0;  // reset for next graph replay
    }
}

extern "C" void kernel_launch(void* const* d_in, const int* in_sizes, int n_in,
                              void* d_out, int out_size) {
    const float* x = (const float*)d_in[0];
    const float* W1 = (const float*)d_in[1];
    const float* b1 = (const float*)d_in[2];
    const float* w2 = (const float*)d_in[3];
    const float* b2 = (const float*)d_in[4];
    int N = in_sizes[0] / 2;

    pde_main<<<(N / CTA_PTS) * 2, TPB>>>(x, W1, b1, w2, b2, (float*)d_out, N);
}